// round 3
// baseline (speedup 1.0000x reference)
#include <cuda_runtime.h>
#include <math.h>
#include <stdint.h>

// Problem constants
#define NNODE 8192
#define NEDGE 131072
#define NTOT  (NNODE + NEDGE)   // 139264
#define HDIM  128
#define H3    384
#define MDIM  64

// ---------------- device scratch (static globals: allowed) ----------------
__device__ float g_x  [(size_t)NTOT * HDIM];
__device__ float g_m  [(size_t)NTOT * HDIM];   // reused as hm1
__device__ float g_agg[(size_t)NTOT * HDIM];   // reused as hm2
__device__ float g_gi [(size_t)NTOT * H3];     // reused as msgs
__device__ float g_gh [(size_t)NTOT * H3];
__device__ float g_nm [NNODE * MDIM];

__device__ int g_deg_var[NNODE], g_off_var[NNODE + 1], g_cur_var[NNODE];
__device__ int g_lst_var[2 * NEDGE];
__device__ int g_deg_row[NNODE], g_off_row[NNODE + 1], g_cur_row[NNODE];
__device__ int g_lst_row[NEDGE];

// ---------------- small helper kernels ----------------
__global__ void zero_deg_kernel(int* degv, int* degr) {
    int i = blockIdx.x * blockDim.x + threadIdx.x;
    if (i < NNODE) { degv[i] = 0; degr[i] = 0; }
}

__global__ void count_kernel(const int* __restrict__ row, const int* __restrict__ col,
                             int* degv, int* degr) {
    int e = blockIdx.x * blockDim.x + threadIdx.x;
    if (e < NEDGE) {
        atomicAdd(&degv[row[e]], 1);
        atomicAdd(&degv[col[e]], 1);
        atomicAdd(&degr[row[e]], 1);
    }
}

// exclusive scan of 8192 ints with one 1024-thread block (8 per thread)
__global__ void scan_kernel(const int* __restrict__ deg, int* __restrict__ off) {
    __shared__ int sm[1024];
    int t = threadIdx.x;
    int v[8], pre[8];
    int s = 0;
#pragma unroll
    for (int i = 0; i < 8; i++) {
        v[i] = deg[t * 8 + i];
        pre[i] = s;
        s += v[i];
    }
    sm[t] = s;
    __syncthreads();
    for (int d = 1; d < 1024; d <<= 1) {
        int add = 0;
        if (t >= d) add = sm[t - d];
        __syncthreads();
        sm[t] += add;
        __syncthreads();
    }
    int base = (t == 0) ? 0 : sm[t - 1];
#pragma unroll
    for (int i = 0; i < 8; i++) off[t * 8 + i] = base + pre[i];
    if (t == 1023) off[8192] = sm[1023];
}

__global__ void copy_cur_kernel(const int* offv, int* curv, const int* offr, int* curr) {
    int i = blockIdx.x * blockDim.x + threadIdx.x;
    if (i < NNODE) { curv[i] = offv[i]; curr[i] = offr[i]; }
}

__global__ void scatter_kernel(const int* __restrict__ row, const int* __restrict__ col,
                               int* curv, int* lstv, int* curr, int* lstr) {
    int e = blockIdx.x * blockDim.x + threadIdx.x;
    if (e < NEDGE) {
        int r = row[e], c = col[e];
        int p = atomicAdd(&curv[r], 1); lstv[p] = e;
        int q = atomicAdd(&curv[c], 1); lstv[q] = e;
        int u = atomicAdd(&curr[r], 1); lstr[u] = e;
    }
}

__global__ void init_x_kernel(float* __restrict__ x, const float* __restrict__ jvals) {
    int idx = blockIdx.x * blockDim.x + threadIdx.x;
    int n = idx >> 7, h = idx & 127;
    float v = 0.0f;
    if (n >= NNODE) {
        if (h == 0) v = 1.0f;
        else if (h == 1) v = jvals[n - NNODE];
    }
    x[(size_t)idx] = v;
}

// agg for factor rows: agg[NNODE+e] = m[row[e]] + m[col[e]]
__global__ void factor_agg_kernel(const float* __restrict__ m,
                                  const int* __restrict__ row, const int* __restrict__ col,
                                  float* __restrict__ agg) {
    int t = blockIdx.x * blockDim.x + threadIdx.x;
    int e = t >> 5, q = t & 31;
    const float4* m4 = (const float4*)m;
    float4* a4 = (float4*)agg;
    int r = row[e], c = col[e];
    float4 a = m4[(size_t)r * 32 + q];
    float4 b = m4[(size_t)c * 32 + q];
    a4[(size_t)(NNODE + e) * 32 + q] = make_float4(a.x + b.x, a.y + b.y, a.z + b.z, a.w + b.w);
}

// agg for variable rows: sum over incident factor messages (CSR)
__global__ void var_agg_kernel(const float* __restrict__ m,
                               const int* __restrict__ off, const int* __restrict__ lst,
                               float* __restrict__ agg) {
    int v = blockIdx.x;
    int h = threadIdx.x;
    int s = off[v], e = off[v + 1];
    float acc = 0.0f;
    for (int p = s; p < e; p++) {
        int ed = lst[p];
        acc += m[(size_t)(NNODE + ed) * HDIM + h];
    }
    agg[(size_t)v * HDIM + h] = acc;
}

// node_msgs: segment_sum(msgs, row) over n_nodes (CSR of row only)
__global__ void node_msgs_kernel(const float* __restrict__ msgs,
                                 const int* __restrict__ off, const int* __restrict__ lst,
                                 float* __restrict__ nm) {
    int v = blockIdx.x;
    int h = threadIdx.x;   // 64
    int s = off[v], e = off[v + 1];
    float acc = 0.0f;
    for (int p = s; p < e; p++) {
        int ed = lst[p];
        acc += msgs[(size_t)ed * MDIM + h];
    }
    nm[v * MDIM + h] = acc;
}

// fused GRU elementwise update (biases already added in GEMM epilogue)
__global__ void gru_kernel(const float* __restrict__ gi, const float* __restrict__ gh,
                           float* __restrict__ x) {
    int idx = blockIdx.x * blockDim.x + threadIdx.x;
    int n = idx >> 7, h = idx & 127;
    size_t b = (size_t)n * H3;
    float ir = gi[b + h],        hr = gh[b + h];
    float iz = gi[b + HDIM + h], hz = gh[b + HDIM + h];
    float in_ = gi[b + 2 * HDIM + h], hn = gh[b + 2 * HDIM + h];
    float r = 1.0f / (1.0f + expf(-(ir + hr)));
    float z = 1.0f / (1.0f + expf(-(iz + hz)));
    float nn = tanhf(in_ + r * hn);
    x[(size_t)idx] = (1.0f - z) * nn + z * x[(size_t)idx];
}

// ---------------- tiled SGEMM ----------------
// C[M,N] = A[M,K] * B (+bias, optional relu)
// bT = 0: B is K x N row-major (ldb = N).  bT = 1: B is N x K row-major (ldb = K).
// BM=128 BN=64 BK=16, 256 threads, 8x4 micro-tile. M%128==0, N%64==0, K%16==0.
__global__ void sgemm_kernel(const float* __restrict__ A, const float* __restrict__ B,
                             const float* __restrict__ bias, float* __restrict__ C,
                             int M, int N, int K, int ldb, int bT, int doRelu) {
    __shared__ float As[16 * 128];   // [k][m]
    __shared__ float Bs[16 * 64];    // [k][n]
    int tid = threadIdx.x;
    int bn = blockIdx.x * 64;
    int bm = blockIdx.y * 128;
    int tx = tid & 15;   // n micro
    int ty = tid >> 4;   // m micro
    int arow = tid & 63, acg = tid >> 6;      // A load mapping
    float acc[8][4];
#pragma unroll
    for (int i = 0; i < 8; i++)
#pragma unroll
        for (int j = 0; j < 4; j++) acc[i][j] = 0.0f;

    for (int kt = 0; kt < K; kt += 16) {
        // load A tile 128x16 (two passes of 64 rows)
#pragma unroll
        for (int p = 0; p < 2; p++) {
            int r = arow + p * 64;
            float4 v = *(const float4*)&A[(size_t)(bm + r) * K + kt + acg * 4];
            As[(acg * 4 + 0) * 128 + r] = v.x;
            As[(acg * 4 + 1) * 128 + r] = v.y;
            As[(acg * 4 + 2) * 128 + r] = v.z;
            As[(acg * 4 + 3) * 128 + r] = v.w;
        }
        // load B tile 16x64
        if (bT) {
            int n = tid & 63, kg = tid >> 6;
            float4 v = *(const float4*)&B[(size_t)(bn + n) * ldb + kt + kg * 4];
            Bs[(kg * 4 + 0) * 64 + n] = v.x;
            Bs[(kg * 4 + 1) * 64 + n] = v.y;
            Bs[(kg * 4 + 2) * 64 + n] = v.z;
            Bs[(kg * 4 + 3) * 64 + n] = v.w;
        } else {
            int n4 = tid & 15, k = tid >> 4;
            float4 v = *(const float4*)&B[(size_t)(kt + k) * ldb + bn + n4 * 4];
            *(float4*)&Bs[k * 64 + n4 * 4] = v;
        }
        __syncthreads();
#pragma unroll
        for (int kk = 0; kk < 16; kk++) {
            float4 b4 = *(const float4*)&Bs[kk * 64 + tx * 4];
            float4 a0 = *(const float4*)&As[kk * 128 + ty * 8];
            float4 a1 = *(const float4*)&As[kk * 128 + ty * 8 + 4];
            float ar[8] = {a0.x, a0.y, a0.z, a0.w, a1.x, a1.y, a1.z, a1.w};
#pragma unroll
            for (int i = 0; i < 8; i++) {
                acc[i][0] += ar[i] * b4.x;
                acc[i][1] += ar[i] * b4.y;
                acc[i][2] += ar[i] * b4.z;
                acc[i][3] += ar[i] * b4.w;
            }
        }
        __syncthreads();
    }

    float4 bb = make_float4(0.f, 0.f, 0.f, 0.f);
    if (bias) bb = *(const float4*)&bias[bn + tx * 4];
#pragma unroll
    for (int i = 0; i < 8; i++) {
        float4 o;
        o.x = acc[i][0] + bb.x;
        o.y = acc[i][1] + bb.y;
        o.z = acc[i][2] + bb.z;
        o.w = acc[i][3] + bb.w;
        if (doRelu) {
            o.x = fmaxf(o.x, 0.f); o.y = fmaxf(o.y, 0.f);
            o.z = fmaxf(o.z, 0.f); o.w = fmaxf(o.w, 0.f);
        }
        *(float4*)&C[(size_t)(bm + ty * 8 + i) * N + bn + tx * 4] = o;
    }
}

// ---------------- fused readout: 2 dense layers + logits + softmax ----------------
#define NPB 16
__global__ void readout_kernel(const float* __restrict__ nm,
                               const float* __restrict__ W1, const float* __restrict__ b1,
                               const float* __restrict__ W2, const float* __restrict__ b2,
                               const float* __restrict__ W3, const float* __restrict__ b3,
                               float* __restrict__ out) {
    __shared__ float nms[64], h1s[128], h2s[128], red[128];
    __shared__ float l0sh;
    int t = threadIdx.x;   // 128
    int v0 = blockIdx.x * NPB;
    for (int v = v0; v < v0 + NPB; v++) {
        if (t < 64) nms[t] = nm[v * MDIM + t];
        __syncthreads();
        float a = b1[t];
#pragma unroll 4
        for (int k = 0; k < 64; k++) a += nms[k] * W1[k * 128 + t];
        h1s[t] = fmaxf(a, 0.f);
        __syncthreads();
        float c = b2[t];
#pragma unroll 4
        for (int k = 0; k < 128; k++) c += h1s[k] * W2[k * 128 + t];
        h2s[t] = fmaxf(c, 0.f);
        __syncthreads();
        // logit 0
        red[t] = h2s[t] * W3[2 * t + 0];
        __syncthreads();
        for (int s = 64; s > 0; s >>= 1) {
            if (t < s) red[t] += red[t + s];
            __syncthreads();
        }
        if (t == 0) l0sh = red[0] + b3[0];
        __syncthreads();
        // logit 1
        red[t] = h2s[t] * W3[2 * t + 1];
        __syncthreads();
        for (int s = 64; s > 0; s >>= 1) {
            if (t < s) red[t] += red[t + s];
            __syncthreads();
        }
        if (t == 0) {
            float l0 = l0sh;
            float l1 = red[0] + b3[1];
            float mx = fmaxf(l0, l1);
            float e0 = expf(l0 - mx), e1 = expf(l1 - mx);
            float s_ = e0 + e1;
            out[v * 2 + 0] = e0 / s_;
            out[v * 2 + 1] = e1 / s_;
        }
        __syncthreads();
    }
}

// ---------------- launch ----------------
extern "C" void kernel_launch(void* const* d_in, const int* in_sizes, int n_in,
                              void* d_out, int out_size) {
    const float* jvals = (const float*)d_in[0];
    // d_in[1] = b (unused: only defines n_nodes)
    const int* row = (const int*)d_in[2];
    const int* col = (const int*)d_in[3];
    const float* convW  = (const float*)d_in[4];
    const float* gru_wi = (const float*)d_in[5];
    const float* gru_wh = (const float*)d_in[6];
    const float* gru_bi = (const float*)d_in[7];
    const float* gru_bh = (const float*)d_in[8];
    const float* mp_W1 = (const float*)d_in[9];
    const float* mp_b1 = (const float*)d_in[10];
    const float* mp_W2 = (const float*)d_in[11];
    const float* mp_b2 = (const float*)d_in[12];
    const float* mp_W3 = (const float*)d_in[13];
    const float* mp_b3 = (const float*)d_in[14];
    const float* ro_W1 = (const float*)d_in[15];
    const float* ro_b1 = (const float*)d_in[16];
    const float* ro_W2 = (const float*)d_in[17];
    const float* ro_b2 = (const float*)d_in[18];
    const float* ro_W3 = (const float*)d_in[19];
    const float* ro_b3 = (const float*)d_in[20];
    float* out = (float*)d_out;

    float *x, *m, *agg, *gi, *gh, *nm;
    int *degv, *offv, *curv, *lstv, *degr, *offr, *curr, *lstr;
    cudaGetSymbolAddress((void**)&x,   g_x);
    cudaGetSymbolAddress((void**)&m,   g_m);
    cudaGetSymbolAddress((void**)&agg, g_agg);
    cudaGetSymbolAddress((void**)&gi,  g_gi);
    cudaGetSymbolAddress((void**)&gh,  g_gh);
    cudaGetSymbolAddress((void**)&nm,  g_nm);
    cudaGetSymbolAddress((void**)&degv, g_deg_var);
    cudaGetSymbolAddress((void**)&offv, g_off_var);
    cudaGetSymbolAddress((void**)&curv, g_cur_var);
    cudaGetSymbolAddress((void**)&lstv, g_lst_var);
    cudaGetSymbolAddress((void**)&degr, g_deg_row);
    cudaGetSymbolAddress((void**)&offr, g_off_row);
    cudaGetSymbolAddress((void**)&curr, g_cur_row);
    cudaGetSymbolAddress((void**)&lstr, g_lst_row);

    // ---- CSR build (per launch; deterministic work, fp-order only varies) ----
    zero_deg_kernel<<<NNODE / 256, 256>>>(degv, degr);
    count_kernel<<<NEDGE / 256, 256>>>(row, col, degv, degr);
    scan_kernel<<<1, 1024>>>(degv, offv);
    scan_kernel<<<1, 1024>>>(degr, offr);
    copy_cur_kernel<<<NNODE / 256, 256>>>(offv, curv, offr, curr);
    scatter_kernel<<<NEDGE / 256, 256>>>(row, col, curv, lstv, curr, lstr);

    // ---- init x ----
    init_x_kernel<<<(NTOT * HDIM) / 256, 256>>>(x, jvals);

    // ---- 2 GGNN layers ----
    for (int l = 0; l < 2; l++) {
        // m = x @ conv_W[l]            (NN layout)
        sgemm_kernel<<<dim3(HDIM / 64, NTOT / 128), 256>>>(
            x, convW + (size_t)l * HDIM * HDIM, nullptr, m, NTOT, HDIM, HDIM, HDIM, 0, 0);
        // agg = segment_sum(m[src], dst)
        factor_agg_kernel<<<(NEDGE * 32) / 128, 128>>>(m, row, col, agg);
        var_agg_kernel<<<NNODE, 128>>>(m, offv, lstv, agg);
        // gi = agg @ wi^T + bi, gh = x @ wh^T + bh  (TN layout)
        sgemm_kernel<<<dim3(H3 / 64, NTOT / 128), 256>>>(
            agg, gru_wi, gru_bi, gi, NTOT, H3, HDIM, HDIM, 1, 0);
        sgemm_kernel<<<dim3(H3 / 64, NTOT / 128), 256>>>(
            x, gru_wh, gru_bh, gh, NTOT, H3, HDIM, HDIM, 1, 0);
        gru_kernel<<<(NTOT * HDIM) / 256, 256>>>(gi, gh, x);
    }

    // ---- edge MLP on factor rows ----
    const float* xf = x + (size_t)NNODE * HDIM;
    sgemm_kernel<<<dim3(HDIM / 64, NEDGE / 128), 256>>>(
        xf, mp_W1, mp_b1, m, NEDGE, HDIM, HDIM, HDIM, 0, 1);
    sgemm_kernel<<<dim3(HDIM / 64, NEDGE / 128), 256>>>(
        m, mp_W2, mp_b2, agg, NEDGE, HDIM, HDIM, HDIM, 0, 1);
    sgemm_kernel<<<dim3(MDIM / 64, NEDGE / 128), 256>>>(
        agg, mp_W3, mp_b3, gi, NEDGE, MDIM, HDIM, MDIM, 0, 0);

    // ---- node_msgs = segment_sum(msgs, row) ----
    node_msgs_kernel<<<NNODE, 64>>>(gi, offr, lstr, nm);

    // ---- readout + softmax ----
    readout_kernel<<<NNODE / NPB, 128>>>(nm, ro_W1, ro_b1, ro_W2, ro_b2, ro_W3, ro_b3, out);
}